// round 5
// baseline (speedup 1.0000x reference)
#include <cuda_runtime.h>

#define Bn 512
#define Tn 512
#define Kn 64

// Scratch (no allocations allowed -> device globals)
__device__ int g_seq[Bn];
__device__ float g_rangeT;  // safe-padded (maxT - minT) over the transition matrix

// ---------------------------------------------------------------------------
// Monotone float <-> uint order-preserving map (finite floats).
// ---------------------------------------------------------------------------
__device__ __forceinline__ unsigned fmap(float f) {
    int i = __float_as_int(f);
    return (unsigned)(i >= 0 ? (i ^ 0x80000000) : ~i);
}
__device__ __forceinline__ float funmap(unsigned u) {
    int i = (u & 0x80000000u) ? (int)(u ^ 0x80000000u) : ~(int)u;
    return __int_as_float(i);
}

// ---------------------------------------------------------------------------
// Kernel 0: padded range of transitions (exclusion-safety bound).
// ---------------------------------------------------------------------------
__global__ __launch_bounds__(256) void transrange_kernel(const float* __restrict__ tr) {
    __shared__ float smin[256], smax[256];
    float lo = tr[threadIdx.x], hi = lo;
    for (int i = threadIdx.x; i < Kn * Kn; i += 256) {
        float v = tr[i];
        lo = fminf(lo, v);
        hi = fmaxf(hi, v);
    }
    smin[threadIdx.x] = lo; smax[threadIdx.x] = hi;
    __syncthreads();
    for (int s = 128; s > 0; s >>= 1) {
        if (threadIdx.x < s) {
            smin[threadIdx.x] = fminf(smin[threadIdx.x], smin[threadIdx.x + s]);
            smax[threadIdx.x] = fmaxf(smax[threadIdx.x], smax[threadIdx.x + s]);
        }
        __syncthreads();
    }
    if (threadIdx.x == 0) {
        float r = smax[0] - smin[0];
        g_rangeT = r + fabsf(r) * 1e-5f + 1e-4f;  // pad: only ever ADDS candidates
    }
}

// ---------------------------------------------------------------------------
// Kernel 1: seq_lens[b] = int( mean_k( sum_t (x[b,t,k] != 0) ) )  (exact)
// ---------------------------------------------------------------------------
__global__ __launch_bounds__(256) void seqlen_kernel(const float* __restrict__ x) {
    __shared__ int red[256];
    const int b = blockIdx.x;
    const float4* xb = (const float4*)(x + (size_t)b * Tn * Kn);
    int c = 0;
    for (int i = threadIdx.x; i < (Tn * Kn) / 4; i += 256) {
        float4 v = xb[i];
        c += (v.x != 0.0f) + (v.y != 0.0f) + (v.z != 0.0f) + (v.w != 0.0f);
    }
    red[threadIdx.x] = c;
    __syncthreads();
    for (int s = 128; s > 0; s >>= 1) {
        if (threadIdx.x < s) red[threadIdx.x] += red[threadIdx.x + s];
        __syncthreads();
    }
    if (threadIdx.x == 0) g_seq[b] = red[0] >> 6;  // floor(total / 64)
}

// ---------------------------------------------------------------------------
// Kernel 2: Viterbi with provably-safe candidate pruning.
// One block per batch, thread = to-tag j. Candidate from-tags i are those with
// alpha[i] >= warpmax(alpha) - rangeT: every excluded i loses STRICTLY to the
// warp-max tag for all j, so first-max argmax over the ordered candidate set
// is bit-identical to the full argmax.
// ---------------------------------------------------------------------------
__global__ __launch_bounds__(Kn) void viterbi_kernel(
    const float* __restrict__ pots,   // [B, T, K]
    const float* __restrict__ trans,  // [K, K]
    float* __restrict__ out)          // [B, T] float32
{
    extern __shared__ float trans_s[];           // [Kn*Kn] dynamic (16 KB)
    __shared__ __align__(16) float alpha[2][Kn]; // double buffer
    __shared__ unsigned masks_s[2][2];           // [buf][warp]
    __shared__ unsigned char bp[(Tn - 1) * Kn];
    __shared__ unsigned char tags[Tn];

    const int b = blockIdx.x;
    const int j = threadIdx.x;
    const int w = j >> 5;
    const int lane = j & 31;

    // Stage transitions into smem (conflict-free 4B-stride reads later).
    for (int i = j; i < Kn * Kn; i += Kn) trans_s[i] = trans[i];

    const float* pb = pots + (size_t)b * Tn * Kn;
    const float rT = g_rangeT;
    int sl = g_seq[b];
    if (sl > Tn) sl = Tn;

    // alpha0 + initial candidate masks
    float aj = pb[j];
    alpha[0][j] = aj;
    {
        unsigned wm = __reduce_max_sync(0xffffffffu, fmap(aj));
        float thr = funmap(wm) - rT;
        unsigned bal = __ballot_sync(0xffffffffu, aj >= thr);
        if (lane == 0) masks_s[0][w] = bal;
    }
    __syncthreads();

    float p1 = pb[Kn + j];          // potentials, 2 steps of prefetch
    float p2 = pb[2 * Kn + j];

    int cur = 0;
    unsigned m0 = masks_s[0][0], m1 = masks_s[0][1];

    for (int t = 1; t < Tn; t++) {
        const float p = p1;
        p1 = p2;
        const int tn = (t + 2 < Tn) ? (t + 2) : (Tn - 1);
        p2 = pb[tn * Kn + j];

        int bi;
        if (t < sl) {
            const float* arow = alpha[cur];
            float best = -3.402823466e38f;
            bi = 0;
            unsigned m = m0;           // masks are uniform -> no divergence
            while (m) {
                const int i = __ffs(m) - 1;
                m &= m - 1;
                const float s = arow[i] + trans_s[i * Kn + j];
                const bool g = s > best;         // strict: first max wins
                best = g ? s : best;
                bi = g ? i : bi;
            }
            m = m1;
            while (m) {
                const int i = 32 + __ffs(m) - 1;
                m &= m - 1;
                const float s = arow[i] + trans_s[i * Kn + j];
                const bool g = s > best;
                best = g ? s : best;
                bi = g ? i : bi;
            }
            aj = p + best;             // same fp32 op order as reference
        } else {
            bi = j;                    // frozen: identity backpointer, aj kept
        }

        bp[(t - 1) * Kn + j] = (unsigned char)bi;
        alpha[cur ^ 1][j] = aj;

        // Per-warp threshold for the NEXT step (warp max <= block max: safe).
        unsigned wm = __reduce_max_sync(0xffffffffu, fmap(aj));
        float thr = funmap(wm) - rT;
        unsigned bal = __ballot_sync(0xffffffffu, aj >= thr);
        if (lane == 0) masks_s[cur ^ 1][w] = bal;

        cur ^= 1;
        __syncthreads();
        m0 = masks_s[cur][0];
        m1 = masks_s[cur][1];
    }

    // Backtrace (SMEM pointer-chase) by thread 0. First max wins.
    if (j == 0) {
        float bv = alpha[cur][0];
        int bt = 0;
#pragma unroll 1
        for (int i = 1; i < Kn; i++) {
            float v = alpha[cur][i];
            if (v > bv) { bv = v; bt = i; }
        }
        int tg = bt;
        tags[Tn - 1] = (unsigned char)tg;
#pragma unroll 1
        for (int t = Tn - 2; t >= 0; t--) {
            tg = bp[t * Kn + tg];
            tags[t] = (unsigned char)tg;
        }
    }
    __syncthreads();

    // Coalesced float32 output write.
    float* ob = out + (size_t)b * Tn;
#pragma unroll
    for (int t = j; t < Tn; t += Kn) ob[t] = (float)tags[t];
}

// ---------------------------------------------------------------------------
extern "C" void kernel_launch(void* const* d_in, const int* in_sizes, int n_in,
                              void* d_out, int out_size) {
    const float* inputs = nullptr;
    const float* transitions = nullptr;
    for (int i = 0; i < n_in; i++) {
        if (in_sizes[i] == Kn * Kn) transitions = (const float*)d_in[i];
        else if (in_sizes[i] == Bn * Tn * Kn) inputs = (const float*)d_in[i];
    }
    if (!inputs) inputs = (const float*)d_in[0];
    if (!transitions) transitions = (const float*)d_in[1];

    float* out = (float*)d_out;

    // Static smem (~33.7 KB) + 16 KB dynamic exceeds the 48 KB default
    // dynamic-smem cap -> must opt in. Host-side config call, NOT a stream
    // op: invisible to graph capture, idempotent, deterministic.
    cudaFuncSetAttribute(viterbi_kernel,
                         cudaFuncAttributeMaxDynamicSharedMemorySize,
                         Kn * Kn * (int)sizeof(float));

    transrange_kernel<<<1, 256>>>(transitions);
    seqlen_kernel<<<Bn, 256>>>(inputs);
    viterbi_kernel<<<Bn, Kn, Kn * Kn * sizeof(float)>>>(inputs, transitions, out);
}

// round 6
// speedup vs baseline: 1.2581x; 1.2581x over previous
#include <cuda_runtime.h>
#include <cfloat>

#define Bn 512
#define Tn 512
#define Kn 64
#define PD 8  // potentials prefetch depth (ring in registers)

// Scratch (no allocations allowed -> device global)
__device__ int g_seq[Bn];

// Monotone float <-> uint order-preserving map (finite floats).
__device__ __forceinline__ unsigned fmap(float f) {
    int i = __float_as_int(f);
    return (unsigned)(i >= 0 ? (i ^ 0x80000000) : ~i);
}
__device__ __forceinline__ float funmap(unsigned u) {
    int i = (u & 0x80000000u) ? (int)(u ^ 0x80000000u) : ~(int)u;
    return __int_as_float(i);
}

// ---------------------------------------------------------------------------
// Kernel 1: seq_lens[b] = int( mean_k( sum_t (x[b,t,k] != 0) ) )  (exact)
// ---------------------------------------------------------------------------
__global__ __launch_bounds__(256) void seqlen_kernel(const float* __restrict__ x) {
    __shared__ int red[256];
    const int b = blockIdx.x;
    const float4* xb = (const float4*)(x + (size_t)b * Tn * Kn);
    int c = 0;
    for (int i = threadIdx.x; i < (Tn * Kn) / 4; i += 256) {
        float4 v = xb[i];
        c += (v.x != 0.0f) + (v.y != 0.0f) + (v.z != 0.0f) + (v.w != 0.0f);
    }
    red[threadIdx.x] = c;
    __syncthreads();
    for (int s = 128; s > 0; s >>= 1) {
        if (threadIdx.x < s) red[threadIdx.x] += red[threadIdx.x + s];
        __syncthreads();
    }
    if (threadIdx.x == 0) g_seq[b] = red[0] >> 6;  // floor(total / 64)
}

// ---------------------------------------------------------------------------
// Kernel 2: single-warp Viterbi. Thread l owns to-tags {l, l+32}; alpha in
// registers; candidates via shuffle; masks via ballot; no __syncthreads.
// Pruning: candidates = { i : alpha[i] >= max(alpha) - rT }. Excluded i lose
// STRICTLY for every to-tag -> ascending first-max over candidates is
// bit-identical to the full jnp.argmax.
// ---------------------------------------------------------------------------

// One candidate (from-tag i_, ascending): updates both to-tag accumulators.
#define SCAN_BODY(i_)                                                        \
    {                                                                        \
        const float asel_ = ((i_) < 32) ? a_lo : a_hi; /* uniform select */  \
        const float ai_ = __shfl_sync(0xffffffffu, asel_, (i_) & 31);        \
        const float2 tv_ = trans2[(i_) * 32 + l];                            \
        const float s0_ = ai_ + tv_.x;                                       \
        const float s1_ = ai_ + tv_.y;                                       \
        const bool g0_ = s0_ > best_lo;                                      \
        best_lo = g0_ ? s0_ : best_lo;  bi_lo = g0_ ? (i_) : bi_lo;          \
        const bool g1_ = s1_ > best_hi;                                      \
        best_hi = g1_ ? s1_ : best_hi;  bi_hi = g1_ ? (i_) : bi_hi;          \
    }

// One DP step at time t_ with compile-time ring slot S_.
#define STEP(T_, S_)                                                         \
    {                                                                        \
        const int t_ = (T_);                                                 \
        const float p_lo = plo[S_];                                          \
        const float p_hi = phi[S_];                                          \
        const int tl_ = (t_ + PD <= Tn - 1) ? (t_ + PD) : (Tn - 1);          \
        plo[S_] = pb[tl_ * Kn + l];                                          \
        phi[S_] = pb[tl_ * Kn + 32 + l];                                     \
        int bi_lo, bi_hi;                                                    \
        if (t_ < sl) {                                                       \
            float best_lo = -FLT_MAX, best_hi = -FLT_MAX;                    \
            bi_lo = 0; bi_hi = 0;                                            \
            unsigned long long M_ =                                          \
                ((unsigned long long)m_hi << 32) | (unsigned long long)m_lo; \
            while (M_) {                                                     \
                const int i_ = __ffsll((long long)M_) - 1;                   \
                M_ &= M_ - 1;                                                \
                SCAN_BODY(i_);                                               \
            }                                                                \
            a_lo = p_lo + best_lo;                                           \
            a_hi = p_hi + best_hi;                                           \
        } else {                                                             \
            bi_lo = l; bi_hi = l + 32;  /* identity backptr, alpha frozen */ \
        }                                                                    \
        bp[(t_ - 1) * Kn + l] = (unsigned char)bi_lo;                        \
        bp[(t_ - 1) * Kn + 32 + l] = (unsigned char)bi_hi;                   \
        const unsigned am_ = fmap(a_lo), ah_ = fmap(a_hi);                   \
        const unsigned wm_ =                                                 \
            __reduce_max_sync(0xffffffffu, am_ > ah_ ? am_ : ah_);           \
        const float thr_ = funmap(wm_) - rT;                                 \
        m_lo = __ballot_sync(0xffffffffu, a_lo >= thr_);                     \
        m_hi = __ballot_sync(0xffffffffu, a_hi >= thr_);                     \
    }

__global__ __launch_bounds__(32) void viterbi_kernel(
    const float* __restrict__ pots,   // [B, T, K]
    const float* __restrict__ trans,  // [K, K]
    float* __restrict__ out)          // [B, T] float32
{
    extern __shared__ float2 trans2[];            // [64][32]: (T[i][l], T[i][l+32]), 16 KB
    __shared__ unsigned char bp[(Tn - 1) * Kn];   // 32704 B
    __shared__ unsigned char tags[Tn];
    __shared__ float alpha_f[Kn];

    const int b = blockIdx.x;
    const int l = threadIdx.x;  // lane; owns to-tags l and l+32

    // ---- Prologue: stage transitions (float2-packed) + padded range ----
    const float4* tr4 = (const float4*)trans;  // 1024 float4
    float tmin = FLT_MAX, tmax = -FLT_MAX;
#pragma unroll
    for (int q = 0; q < 32; q++) {
        const int idx = q * 32 + l;
        const float4 v = tr4[idx];
        tmin = fminf(tmin, fminf(fminf(v.x, v.y), fminf(v.z, v.w)));
        tmax = fmaxf(tmax, fmaxf(fmaxf(v.x, v.y), fmaxf(v.z, v.w)));
        const int base = idx * 4;
        const int i = base >> 6;
        const int c = base & 63;      // 4-aligned; never straddles 32
        if (c < 32) {
            trans2[i * 32 + c + 0].x = v.x;
            trans2[i * 32 + c + 1].x = v.y;
            trans2[i * 32 + c + 2].x = v.z;
            trans2[i * 32 + c + 3].x = v.w;
        } else {
            const int cc = c - 32;
            trans2[i * 32 + cc + 0].y = v.x;
            trans2[i * 32 + cc + 1].y = v.y;
            trans2[i * 32 + cc + 2].y = v.z;
            trans2[i * 32 + cc + 3].y = v.w;
        }
    }
    const unsigned rmn = __reduce_min_sync(0xffffffffu, fmap(tmin));
    const unsigned rmx = __reduce_max_sync(0xffffffffu, fmap(tmax));
    const float r = funmap(rmx) - funmap(rmn);
    const float rT = r + fabsf(r) * 1e-5f + 0.01f;  // pad only ADDS candidates
    __syncwarp();

    const float* pb = pots + (size_t)b * Tn * Kn;
    int sl = g_seq[b];
    if (sl > Tn) sl = Tn;

    // alpha0 + initial masks
    float a_lo = pb[l];
    float a_hi = pb[32 + l];
    unsigned m_lo, m_hi;
    {
        const unsigned am = fmap(a_lo), ah = fmap(a_hi);
        const unsigned wm = __reduce_max_sync(0xffffffffu, am > ah ? am : ah);
        const float thr = funmap(wm) - rT;
        m_lo = __ballot_sync(0xffffffffu, a_lo >= thr);
        m_hi = __ballot_sync(0xffffffffu, a_hi >= thr);
    }

    // Prefetch ring, depth PD (slot = t & 7, compile-time in every STEP)
    float plo[PD], phi[PD];
#pragma unroll
    for (int d = 1; d <= PD; d++) {
        plo[d & (PD - 1)] = pb[d * Kn + l];
        phi[d & (PD - 1)] = pb[d * Kn + 32 + l];
    }

    // Main DP: t = 1..511, 63 full 8-blocks + 7 remainder (t === 1 mod 8)
    int t = 1;
#pragma unroll 1
    for (int tb = 0; tb < 63; tb++) {
        STEP(t + 0, 1); STEP(t + 1, 2); STEP(t + 2, 3); STEP(t + 3, 4);
        STEP(t + 4, 5); STEP(t + 5, 6); STEP(t + 6, 7); STEP(t + 7, 0);
        t += 8;
    }
    STEP(t + 0, 1); STEP(t + 1, 2); STEP(t + 2, 3); STEP(t + 3, 4);
    STEP(t + 4, 5); STEP(t + 5, 6); STEP(t + 6, 7);

    // Final alpha -> smem for the backtrace scan
    alpha_f[l] = a_lo;
    alpha_f[32 + l] = a_hi;
    __syncwarp();

    // Backtrace (smem pointer-chase) by lane 0. First max wins.
    if (l == 0) {
        float bv = alpha_f[0];
        int bt = 0;
#pragma unroll 1
        for (int i = 1; i < Kn; i++) {
            const float v = alpha_f[i];
            if (v > bv) { bv = v; bt = i; }
        }
        int tg = bt;
        tags[Tn - 1] = (unsigned char)tg;
#pragma unroll 1
        for (int tt = Tn - 2; tt >= 0; tt--) {
            tg = bp[tt * Kn + tg];
            tags[tt] = (unsigned char)tg;
        }
    }
    __syncwarp();

    // Coalesced float32 output write (16 per lane).
    float* ob = out + (size_t)b * Tn;
#pragma unroll
    for (int tt = l; tt < Tn; tt += 32) ob[tt] = (float)tags[tt];
}

// ---------------------------------------------------------------------------
extern "C" void kernel_launch(void* const* d_in, const int* in_sizes, int n_in,
                              void* d_out, int out_size) {
    const float* inputs = nullptr;
    const float* transitions = nullptr;
    for (int i = 0; i < n_in; i++) {
        if (in_sizes[i] == Kn * Kn) transitions = (const float*)d_in[i];
        else if (in_sizes[i] == Bn * Tn * Kn) inputs = (const float*)d_in[i];
    }
    if (!inputs) inputs = (const float*)d_in[0];
    if (!transitions) transitions = (const float*)d_in[1];

    float* out = (float*)d_out;

    // Static (~33.5 KB) + 16 KB dynamic needs the opt-in (host-side config,
    // not a stream op — proven capture-safe in R5).
    cudaFuncSetAttribute(viterbi_kernel,
                         cudaFuncAttributeMaxDynamicSharedMemorySize,
                         Kn * 32 * (int)sizeof(float2));

    seqlen_kernel<<<Bn, 256>>>(inputs);
    viterbi_kernel<<<Bn, 32, Kn * 32 * sizeof(float2)>>>(inputs, transitions, out);
}